// round 1
// baseline (speedup 1.0000x reference)
#include <cuda_runtime.h>
#include <math.h>

#define SEGN 512
#define DDIM 512
#define NLAY 6
#define NSEGS 8
#define FFD 2048
#define MEMN 1024
#define FULLN 1536

// ---------------- scratch (device globals; no allocations allowed) ----------------
__device__ float g_R[FULLN * 512];                 // flipped sinusoid table
__device__ float g_state[2][SEGN * DDIM];          // current segment state per encoder
__device__ float g_hist[2][NLAY][2][SEGN * DDIM];  // layer-input states of last 2 segments
__device__ float g_Ap[2][SEGN * 1024];             // [q+u | q+v]
__device__ float g_kbuf[2][NLAY][FULLN * 1024];    // [k | pk] per layer
__device__ float g_vbuf[2][FULLN * DDIM];          // v
__device__ float g_scores[2][SEGN * FULLN];        // scores / attn (in place)
__device__ float g_av[2][SEGN * DDIM];             // attn @ v
__device__ float g_t[2][SEGN * DDIM];              // state + attn_out@Wo (pre-LN1)
__device__ float g_h[2][SEGN * DDIM];              // post-LN1
__device__ float g_mid[2][SEGN * FFD];             // relu(h@W1)
__device__ float g_t2[2][SEGN * DDIM];             // h + mid@W2 (pre-LN2)

// ---------------- GEMM core: 64x64 tile, BK=16, 4x4 microtile, 256 threads ----------------
#define GEMM_DECL                                                              \
    __shared__ float As[16][68];                                               \
    __shared__ float Bs[16][68];                                               \
    float acc[4][4] = {{0.f,0.f,0.f,0.f},{0.f,0.f,0.f,0.f},                    \
                       {0.f,0.f,0.f,0.f},{0.f,0.f,0.f,0.f}};                   \
    const int t  = threadIdx.x;                                                \
    const int tx = t & 15, ty = t >> 4;                                        \
    const int ar = t >> 2, ac = (t & 3) << 2;                                  \
    const int br = t >> 4, bc = (t & 15) << 2;                                 \
    const int row0 = blockIdx.y << 6, col0 = blockIdx.x << 6;                  \
    (void)br; (void)bc; (void)row0; (void)col0;

#define GEMM_INNER                                                             \
    __syncthreads();                                                           \
    _Pragma("unroll")                                                          \
    for (int kk = 0; kk < 16; ++kk) {                                          \
        float4 a_ = *(const float4*)&As[kk][ty << 2];                          \
        float4 b_ = *(const float4*)&Bs[kk][tx << 2];                          \
        acc[0][0] = fmaf(a_.x, b_.x, acc[0][0]);                               \
        acc[0][1] = fmaf(a_.x, b_.y, acc[0][1]);                               \
        acc[0][2] = fmaf(a_.x, b_.z, acc[0][2]);                               \
        acc[0][3] = fmaf(a_.x, b_.w, acc[0][3]);                               \
        acc[1][0] = fmaf(a_.y, b_.x, acc[1][0]);                               \
        acc[1][1] = fmaf(a_.y, b_.y, acc[1][1]);                               \
        acc[1][2] = fmaf(a_.y, b_.z, acc[1][2]);                               \
        acc[1][3] = fmaf(a_.y, b_.w, acc[1][3]);                               \
        acc[2][0] = fmaf(a_.z, b_.x, acc[2][0]);                               \
        acc[2][1] = fmaf(a_.z, b_.y, acc[2][1]);                               \
        acc[2][2] = fmaf(a_.z, b_.z, acc[2][2]);                               \
        acc[2][3] = fmaf(a_.z, b_.w, acc[2][3]);                               \
        acc[3][0] = fmaf(a_.w, b_.x, acc[3][0]);                               \
        acc[3][1] = fmaf(a_.w, b_.y, acc[3][1]);                               \
        acc[3][2] = fmaf(a_.w, b_.z, acc[3][2]);                               \
        acc[3][3] = fmaf(a_.w, b_.w, acc[3][3]);                               \
    }                                                                          \
    __syncthreads();

// A row-major [M,Ktot] (pre-offset to row0), B row-major [Ktot,N] (pre-offset to col0)
#define GEMM_NN(Aptr, lda, Bptr, ldb, Ktot)                                    \
    for (int kt = 0; kt < (Ktot); kt += 16) {                                  \
        float4 a4 = *(const float4*)((Aptr) + (size_t)ar * (lda) + kt + ac);   \
        As[ac+0][ar] = a4.x; As[ac+1][ar] = a4.y;                              \
        As[ac+2][ar] = a4.z; As[ac+3][ar] = a4.w;                              \
        float4 b4 = *(const float4*)((Bptr) + (size_t)(kt + br) * (ldb) + bc); \
        *(float4*)&Bs[br][bc] = b4;                                            \
        GEMM_INNER                                                             \
    }

// A row-major [M,Ktot] (pre-offset to row0), B row-major [N,Ktot] (pre-offset to col0 rows)
#define GEMM_NT(Aptr, lda, Bptr, ldb, Ktot)                                    \
    for (int kt = 0; kt < (Ktot); kt += 16) {                                  \
        float4 a4 = *(const float4*)((Aptr) + (size_t)ar * (lda) + kt + ac);   \
        As[ac+0][ar] = a4.x; As[ac+1][ar] = a4.y;                              \
        As[ac+2][ar] = a4.z; As[ac+3][ar] = a4.w;                              \
        float4 b4 = *(const float4*)((Bptr) + (size_t)ar * (ldb) + kt + ac);   \
        Bs[ac+0][ar] = b4.x; Bs[ac+1][ar] = b4.y;                              \
        Bs[ac+2][ar] = b4.z; Bs[ac+3][ar] = b4.w;                              \
        GEMM_INNER                                                             \
    }

// ---------------- init: sinusoid table (flipped) ----------------
__global__ void k_R() {
    int i = blockIdx.x;              // output row (already flipped)
    int pos = FULLN - 1 - i;
    for (int d = threadIdx.x; d < 512; d += 256) {
        int i2 = d >> 1;
        float denom = powf(10000.0f, (float)(2 * i2) / 512.0f);
        float ang = (float)pos / denom;
        double a = (double)ang;
        g_R[(size_t)i * 512 + d] = (d & 1) ? (float)cos(a) : (float)sin(a);
    }
}

// pk[e][j] = R @ Wr_j  -> kbuf[e][j][:, 512:1024]
__global__ void __launch_bounds__(256) k_gemm_pk(const float* Wa, const float* Wb) {
    int z = blockIdx.z;
    int e = z / NLAY, layer = z % NLAY;
    GEMM_DECL
    const float* A = g_R + (size_t)row0 * 512;
    const float* B = (e ? Wb : Wa) + ((size_t)layer * 4 + 3) * 512 * 512 + col0;
    GEMM_NN(A, 512, B, 512, 512)
    float* C = g_kbuf[e][layer];
#pragma unroll
    for (int i = 0; i < 4; ++i) {
        float4 o = make_float4(acc[i][0], acc[i][1], acc[i][2], acc[i][3]);
        *(float4*)&C[(size_t)(row0 + (ty << 2) + i) * 1024 + 512 + col0 + (tx << 2)] = o;
    }
}

// state = emb[token]
__global__ void k_embed(const int* src, const float* emb, int s) {
    int e = blockIdx.y, m = blockIdx.x;
    int gpos = s * SEGN + m;
    int tok = e ? src[4095 - gpos] : src[gpos];
    const float4* sr = (const float4*)(emb + (size_t)tok * 512);
    float4* dst = (float4*)(g_state[e] + (size_t)m * 512);
    dst[threadIdx.x] = sr[threadIdx.x];
}

// Ap = [state@Wq + u | state@Wq + v]
__global__ void __launch_bounds__(256) k_gemm_q(const float* Wa, const float* Wb,
                                                const float* uva, const float* uvb, int layer) {
    int e = blockIdx.z;
    GEMM_DECL
    const float* A = g_state[e] + (size_t)row0 * 512;
    const float* B = (e ? Wb : Wa) + ((size_t)layer * 4 + 0) * 512 * 512 + col0;
    const float* uv = e ? uvb : uva;
    GEMM_NN(A, 512, B, 512, 512)
    float* Ap = g_Ap[e];
#pragma unroll
    for (int i = 0; i < 4; ++i) {
        int m = row0 + (ty << 2) + i;
        int n = col0 + (tx << 2);
        float4 o1 = make_float4(acc[i][0] + uv[n], acc[i][1] + uv[n + 1],
                                acc[i][2] + uv[n + 2], acc[i][3] + uv[n + 3]);
        float4 o2 = make_float4(acc[i][0] + uv[512 + n], acc[i][1] + uv[512 + n + 1],
                                acc[i][2] + uv[512 + n + 2], acc[i][3] + uv[512 + n + 3]);
        *(float4*)&Ap[(size_t)m * 1024 + n] = o1;
        *(float4*)&Ap[(size_t)m * 1024 + 512 + n] = o2;
    }
}

// k = full@Wk -> kbuf[:, :512];  v = full@Wv -> vbuf   (full = [hist_old; hist_new; state])
__global__ void __launch_bounds__(256) k_gemm_kv(const float* Wa, const float* Wb,
                                                 int layer, int slot_old, int slot_new) {
    int e = blockIdx.z;
    GEMM_DECL
    const float* A;
    if (row0 < 512)       A = g_hist[e][layer][slot_old] + (size_t)row0 * 512;
    else if (row0 < 1024) A = g_hist[e][layer][slot_new] + (size_t)(row0 - 512) * 512;
    else                  A = g_state[e] + (size_t)(row0 - 1024) * 512;
    const float* Wbase = (e ? Wb : Wa) + (size_t)layer * 4 * 512 * 512;
    const float* B; float* C; int ldc, ccol;
    if (col0 < 512) { B = Wbase + (size_t)1 * 512 * 512 + col0;        C = g_kbuf[e][layer]; ldc = 1024; ccol = col0; }
    else            { B = Wbase + (size_t)2 * 512 * 512 + (col0 - 512); C = g_vbuf[e];       ldc = 512;  ccol = col0 - 512; }
    GEMM_NN(A, 512, B, 512, 512)
#pragma unroll
    for (int i = 0; i < 4; ++i) {
        float4 o = make_float4(acc[i][0], acc[i][1], acc[i][2], acc[i][3]);
        *(float4*)&C[(size_t)(row0 + (ty << 2) + i) * ldc + ccol + (tx << 2)] = o;
    }
}

// record layer-input state into history slot (after kv consumed the old slot)
__global__ void k_copy_rec(int layer, int slot) {
    int e = blockIdx.y, m = blockIdx.x;
    const float4* s4 = (const float4*)(g_state[e] + (size_t)m * 512);
    float4* d4 = (float4*)(g_hist[e][layer][slot] + (size_t)m * 512);
    d4[threadIdx.x] = s4[threadIdx.x];
}

// scores = Ap @ kbuf^T * scale
__global__ void __launch_bounds__(256) k_gemm_scores(int layer) {
    int e = blockIdx.z;
    GEMM_DECL
    const float* A = g_Ap[e] + (size_t)row0 * 1024;
    const float* B = g_kbuf[e][layer] + (size_t)col0 * 1024;
    GEMM_NT(A, 1024, B, 1024, 1024)
    const float scale = 0.04419417382415922f;   // 1/sqrt(512)
    float* C = g_scores[e];
#pragma unroll
    for (int i = 0; i < 4; ++i) {
        float4 o = make_float4(acc[i][0] * scale, acc[i][1] * scale,
                               acc[i][2] * scale, acc[i][3] * scale);
        *(float4*)&C[(size_t)(row0 + (ty << 2) + i) * FULLN + col0 + (tx << 2)] = o;
    }
}

// row softmax over [vstart, 1536); zeros below vstart (== -1e9 bias)
__global__ void k_softmax(int vstart) {
    int e = blockIdx.y, tid = threadIdx.x;
    float* s = g_scores[e] + (size_t)blockIdx.x * FULLN;
    __shared__ float red[256];
    float mx = -3.0e38f;
    for (int c = vstart + tid; c < FULLN; c += 256) mx = fmaxf(mx, s[c]);
    red[tid] = mx; __syncthreads();
    for (int o = 128; o; o >>= 1) { if (tid < o) red[tid] = fmaxf(red[tid], red[tid + o]); __syncthreads(); }
    mx = red[0]; __syncthreads();
    float sum = 0.f;
    for (int c = vstart + tid; c < FULLN; c += 256) { float v = expf(s[c] - mx); s[c] = v; sum += v; }
    red[tid] = sum; __syncthreads();
    for (int o = 128; o; o >>= 1) { if (tid < o) red[tid] += red[tid + o]; __syncthreads(); }
    float inv = 1.f / red[0];
    for (int c = tid; c < vstart; c += 256) s[c] = 0.f;
    for (int c = vstart + tid; c < FULLN; c += 256) s[c] *= inv;
}

// av = attn @ v
__global__ void __launch_bounds__(256) k_gemm_av() {
    int e = blockIdx.z;
    GEMM_DECL
    const float* A = g_scores[e] + (size_t)row0 * FULLN;
    const float* B = g_vbuf[e] + col0;
    GEMM_NN(A, FULLN, B, 512, FULLN)
#pragma unroll
    for (int i = 0; i < 4; ++i) {
        float4 o = make_float4(acc[i][0], acc[i][1], acc[i][2], acc[i][3]);
        *(float4*)&g_av[e][(size_t)(row0 + (ty << 2) + i) * 512 + col0 + (tx << 2)] = o;
    }
}

// t = state + av @ Wo
__global__ void __launch_bounds__(256) k_gemm_wo(const float* Wa, const float* Wb, int layer) {
    int e = blockIdx.z;
    GEMM_DECL
    const float* A = g_av[e] + (size_t)row0 * 512;
    const float* B = (e ? Wb : Wa) + (size_t)layer * 512 * 512 + col0;
    GEMM_NN(A, 512, B, 512, 512)
#pragma unroll
    for (int i = 0; i < 4; ++i) {
        int m = row0 + (ty << 2) + i, n = col0 + (tx << 2);
        float4 st = *(const float4*)&g_state[e][(size_t)m * 512 + n];
        float4 o = make_float4(acc[i][0] + st.x, acc[i][1] + st.y,
                               acc[i][2] + st.z, acc[i][3] + st.w);
        *(float4*)&g_t[e][(size_t)m * 512 + n] = o;
    }
}

// mid = relu(h @ W1)
__global__ void __launch_bounds__(256) k_gemm_w1(const float* Wa, const float* Wb, int layer) {
    int e = blockIdx.z;
    GEMM_DECL
    const float* A = g_h[e] + (size_t)row0 * 512;
    const float* B = (e ? Wb : Wa) + (size_t)layer * 512 * FFD + col0;
    GEMM_NN(A, 512, B, FFD, 512)
#pragma unroll
    for (int i = 0; i < 4; ++i) {
        float4 o = make_float4(fmaxf(acc[i][0], 0.f), fmaxf(acc[i][1], 0.f),
                               fmaxf(acc[i][2], 0.f), fmaxf(acc[i][3], 0.f));
        *(float4*)&g_mid[e][(size_t)(row0 + (ty << 2) + i) * FFD + col0 + (tx << 2)] = o;
    }
}

// t2 = h + mid @ W2
__global__ void __launch_bounds__(256) k_gemm_w2(const float* Wa, const float* Wb, int layer) {
    int e = blockIdx.z;
    GEMM_DECL
    const float* A = g_mid[e] + (size_t)row0 * FFD;
    const float* B = (e ? Wb : Wa) + (size_t)layer * FFD * 512 + col0;
    GEMM_NN(A, FFD, B, 512, FFD)
#pragma unroll
    for (int i = 0; i < 4; ++i) {
        int m = row0 + (ty << 2) + i, n = col0 + (tx << 2);
        float4 hh = *(const float4*)&g_h[e][(size_t)m * 512 + n];
        float4 o = make_float4(acc[i][0] + hh.x, acc[i][1] + hh.y,
                               acc[i][2] + hh.z, acc[i][3] + hh.w);
        *(float4*)&g_t2[e][(size_t)m * 512 + n] = o;
    }
}

// layernorm. mode 0: g_t -> g_h (ln rows 0,1). mode 1: g_t2 -> g_state (ln rows 2,3).
__global__ void k_ln(const float* lnA, const float* lnB, int layer, int which, int mode) {
    int e = blockIdx.y, row = blockIdx.x, tid = threadIdx.x;
    const float* in = (mode ? g_t2[e] : g_t[e]) + (size_t)row * 512;
    float* out = (mode ? g_state[e] : g_h[e]) + (size_t)row * 512;
    const float* ln = (e ? lnB : lnA) + ((size_t)layer * 4 + 2 * which) * 512;
    __shared__ float red[256];
    float x0 = in[tid], x1 = in[tid + 256];
    red[tid] = x0 + x1; __syncthreads();
    for (int o = 128; o; o >>= 1) { if (tid < o) red[tid] += red[tid + o]; __syncthreads(); }
    float mu = red[0] * (1.f / 512.f); __syncthreads();
    float d0 = x0 - mu, d1 = x1 - mu;
    red[tid] = d0 * d0 + d1 * d1; __syncthreads();
    for (int o = 128; o; o >>= 1) { if (tid < o) red[tid] += red[tid + o]; __syncthreads(); }
    float r = rsqrtf(red[0] * (1.f / 512.f) + 1e-5f);
    out[tid]       = d0 * r * ln[tid]       + ln[512 + tid];
    out[tid + 256] = d1 * r * ln[tid + 256] + ln[512 + tid + 256];
}

// last-layer LN2 writes directly to output with fwd/rev mapping
__global__ void k_ln_final(const float* lnA, const float* lnB, int layer, int s, float* out) {
    int e = blockIdx.y, row = blockIdx.x, tid = threadIdx.x;
    const float* in = g_t2[e] + (size_t)row * 512;
    const float* ln = (e ? lnB : lnA) + ((size_t)layer * 4 + 2) * 512;
    __shared__ float red[256];
    float x0 = in[tid], x1 = in[tid + 256];
    red[tid] = x0 + x1; __syncthreads();
    for (int o = 128; o; o >>= 1) { if (tid < o) red[tid] += red[tid + o]; __syncthreads(); }
    float mu = red[0] * (1.f / 512.f); __syncthreads();
    float d0 = x0 - mu, d1 = x1 - mu;
    red[tid] = d0 * d0 + d1 * d1; __syncthreads();
    for (int o = 128; o; o >>= 1) { if (tid < o) red[tid] += red[tid + o]; __syncthreads(); }
    float r = rsqrtf(red[0] * (1.f / 512.f) + 1e-5f);
    int g = s * SEGN + row;
    float* dst = e ? (out + (size_t)(4095 - g) * 1024 + 512) : (out + (size_t)g * 1024);
    dst[tid]       = d0 * r * ln[tid]       + ln[512 + tid];
    dst[tid + 256] = d1 * r * ln[tid + 256] + ln[512 + tid + 256];
}

// ---------------- host orchestration (graph-capturable: launches only) ----------------
extern "C" void kernel_launch(void* const* d_in, const int* in_sizes, int n_in,
                              void* d_out, int out_size) {
    const int*   src  = (const int*)d_in[0];
    const float* emb  = (const float*)d_in[2];
    const float* Wq_a = (const float*)d_in[3];
    const float* Wo_a = (const float*)d_in[4];
    const float* W1_a = (const float*)d_in[5];
    const float* W2_a = (const float*)d_in[6];
    const float* ln_a = (const float*)d_in[7];
    const float* uv_a = (const float*)d_in[8];
    const float* Wq_b = (const float*)d_in[9];
    const float* Wo_b = (const float*)d_in[10];
    const float* W1_b = (const float*)d_in[11];
    const float* W2_b = (const float*)d_in[12];
    const float* ln_b = (const float*)d_in[13];
    const float* uv_b = (const float*)d_in[14];
    float* out = (float*)d_out;

    k_R<<<FULLN, 256>>>();
    k_gemm_pk<<<dim3(8, 24, 12), 256>>>(Wq_a, Wq_b);   // segment-invariant pk, hoisted

    for (int s = 0; s < NSEGS; ++s) {
        k_embed<<<dim3(512, 2), 128>>>(src, emb, s);
        int vstart = 1024 - (s < 2 ? s : 2) * 512;
        int slot_old = s & 1, slot_new = (s & 1) ^ 1;
        for (int j = 0; j < NLAY; ++j) {
            k_gemm_q     <<<dim3(8, 8, 2),   256>>>(Wq_a, Wq_b, uv_a, uv_b, j);
            k_gemm_kv    <<<dim3(16, 24, 2), 256>>>(Wq_a, Wq_b, j, slot_old, slot_new);
            k_copy_rec   <<<dim3(512, 2),    128>>>(j, slot_old);
            k_gemm_scores<<<dim3(24, 8, 2),  256>>>(j);
            k_softmax    <<<dim3(512, 2),    256>>>(vstart);
            k_gemm_av    <<<dim3(8, 8, 2),   256>>>();
            k_gemm_wo    <<<dim3(8, 8, 2),   256>>>(Wo_a, Wo_b, j);
            k_ln         <<<dim3(512, 2),    256>>>(ln_a, ln_b, j, 0, 0);
            k_gemm_w1    <<<dim3(32, 8, 2),  256>>>(W1_a, W1_b, j);
            k_gemm_w2    <<<dim3(8, 8, 2),   256>>>(W2_a, W2_b, j);
            if (j < NLAY - 1) k_ln<<<dim3(512, 2), 256>>>(ln_a, ln_b, j, 1, 1);
            else              k_ln_final<<<dim3(512, 2), 256>>>(ln_a, ln_b, j, s, out);
        }
    }
}

// round 3
// speedup vs baseline: 1.2543x; 1.2543x over previous
#include <cuda_runtime.h>
#include <math.h>

#define SEGN 512
#define DDIM 512
#define NLAY 6
#define NSEGS 8
#define FFD 2048
#define MEMN 1024
#define FULLN 1536

typedef unsigned long long u64;

// ---------------- packed fp32 math (Blackwell FFMA2, PTX-only) ----------------
__device__ __forceinline__ u64 ffma2(u64 a, u64 b, u64 c) {
    u64 d;
    asm("fma.rn.f32x2 %0, %1, %2, %3;" : "=l"(d) : "l"(a), "l"(b), "l"(c));
    return d;
}
__device__ __forceinline__ u64 pack2(float x, float y) {
    u64 d;
    asm("mov.b64 %0, {%1, %2};" : "=l"(d)
        : "r"(__float_as_uint(x)), "r"(__float_as_uint(y)));
    return d;
}
__device__ __forceinline__ float2 unpk(u64 a) {
    unsigned lo, hi;
    asm("mov.b64 {%0, %1}, %2;" : "=r"(lo), "=r"(hi) : "l"(a));
    return make_float2(__uint_as_float(lo), __uint_as_float(hi));
}

// ---------------- scratch (device globals; no allocations allowed) ----------------
__device__ float g_R[FULLN * 512];                 // flipped sinusoid table
__device__ float g_state[2][SEGN * DDIM];          // current segment state per encoder
__device__ float g_hist[2][NLAY][2][SEGN * DDIM];  // layer-input states of last 2 segments
__device__ float g_Ap[2][SEGN * 1024];             // [q+u | q+v]
__device__ float g_kbuf[2][NLAY][FULLN * 1024];    // [k | pk] per layer
__device__ float g_vbuf[2][FULLN * DDIM];          // v
__device__ float g_scores[2][SEGN * FULLN];        // scores / attn (in place)
__device__ float g_av[2][SEGN * DDIM];             // attn @ v
__device__ float g_t[2][SEGN * DDIM];              // state + attn_out@Wo (pre-LN1)
__device__ float g_h[2][SEGN * DDIM];              // post-LN1
__device__ float g_mid[2][SEGN * FFD];             // relu(h@W1)
__device__ float g_t2[2][SEGN * DDIM];             // h + mid@W2 (pre-LN2)

// ---------------- GEMM core: 64x64 tile, BK=16, f32x2 4x4 microtile, 256 thr ----------------
#define GEMM_DECL                                                              \
    __shared__ float As[16][68];                                               \
    __shared__ float Bs[16][68];                                               \
    u64 acc[2][4] = {{0ull,0ull,0ull,0ull},{0ull,0ull,0ull,0ull}};             \
    const int t  = threadIdx.x;                                                \
    const int tx = t & 15, ty = t >> 4;                                        \
    const int ar = t >> 2, ac = (t & 3) << 2;                                  \
    const int br = t >> 4, bc = (t & 15) << 2;                                 \
    const int row0 = blockIdx.y << 6, col0 = blockIdx.x << 6;                  \
    (void)br; (void)bc; (void)row0; (void)col0;

#define INNER16                                                                \
    _Pragma("unroll")                                                          \
    for (int kk = 0; kk < 16; ++kk) {                                          \
        float4 a4 = *(const float4*)&As[kk][ty << 2];                          \
        float4 b4 = *(const float4*)&Bs[kk][tx << 2];                          \
        u64 a01 = pack2(a4.x, a4.y);                                           \
        u64 a23 = pack2(a4.z, a4.w);                                           \
        u64 bb;                                                                \
        bb = pack2(b4.x, b4.x);                                                \
        acc[0][0] = ffma2(a01, bb, acc[0][0]);                                 \
        acc[1][0] = ffma2(a23, bb, acc[1][0]);                                 \
        bb = pack2(b4.y, b4.y);                                                \
        acc[0][1] = ffma2(a01, bb, acc[0][1]);                                 \
        acc[1][1] = ffma2(a23, bb, acc[1][1]);                                 \
        bb = pack2(b4.z, b4.z);                                                \
        acc[0][2] = ffma2(a01, bb, acc[0][2]);                                 \
        acc[1][2] = ffma2(a23, bb, acc[1][2]);                                 \
        bb = pack2(b4.w, b4.w);                                                \
        acc[0][3] = ffma2(a01, bb, acc[0][3]);                                 \
        acc[1][3] = ffma2(a23, bb, acc[1][3]);                                 \
    }

// A row-major [M,Ktot] (pre-offset to row0), B row-major [Ktot,N] (pre-offset to col0)
#define GEMM_NN(Aptr, lda, Bptr, ldb, Ktot) {                                  \
    float4 pa = *(const float4*)((Aptr) + (size_t)ar * (lda) + ac);            \
    float4 pb = *(const float4*)((Bptr) + (size_t)br * (ldb) + bc);            \
    for (int kt = 0; kt < (Ktot); kt += 16) {                                  \
        As[ac+0][ar] = pa.x; As[ac+1][ar] = pa.y;                              \
        As[ac+2][ar] = pa.z; As[ac+3][ar] = pa.w;                              \
        *(float4*)&Bs[br][bc] = pb;                                            \
        __syncthreads();                                                       \
        if (kt + 16 < (Ktot)) {                                                \
            pa = *(const float4*)((Aptr) + (size_t)ar * (lda) + kt + 16 + ac); \
            pb = *(const float4*)((Bptr) + (size_t)(kt + 16 + br) * (ldb) + bc); \
        }                                                                      \
        INNER16                                                                \
        __syncthreads();                                                       \
    } }

// A row-major [M,Ktot] (pre-offset to row0), B row-major [N,Ktot] (pre-offset to col0 rows)
#define GEMM_NT(Aptr, lda, Bptr, ldb, Ktot) {                                  \
    float4 pa = *(const float4*)((Aptr) + (size_t)ar * (lda) + ac);            \
    float4 pb = *(const float4*)((Bptr) + (size_t)ar * (ldb) + ac);            \
    for (int kt = 0; kt < (Ktot); kt += 16) {                                  \
        As[ac+0][ar] = pa.x; As[ac+1][ar] = pa.y;                              \
        As[ac+2][ar] = pa.z; As[ac+3][ar] = pa.w;                              \
        Bs[ac+0][ar] = pb.x; Bs[ac+1][ar] = pb.y;                              \
        Bs[ac+2][ar] = pb.z; Bs[ac+3][ar] = pb.w;                              \
        __syncthreads();                                                       \
        if (kt + 16 < (Ktot)) {                                                \
            pa = *(const float4*)((Aptr) + (size_t)ar * (lda) + kt + 16 + ac); \
            pb = *(const float4*)((Bptr) + (size_t)ar * (ldb) + kt + 16 + ac); \
        }                                                                      \
        INNER16                                                                \
        __syncthreads();                                                       \
    } }

#define GEMM_EPI                                                               \
    float rowv[4][4];                                                          \
    _Pragma("unroll")                                                          \
    for (int c = 0; c < 4; ++c) {                                              \
        float2 v0 = unpk(acc[0][c]);                                           \
        float2 v1 = unpk(acc[1][c]);                                           \
        rowv[0][c] = v0.x; rowv[1][c] = v0.y;                                  \
        rowv[2][c] = v1.x; rowv[3][c] = v1.y;                                  \
    }

// ---------------- init: sinusoid table (flipped) ----------------
__global__ void k_R() {
    int i = blockIdx.x;              // output row (already flipped)
    int pos = FULLN - 1 - i;
    for (int d = threadIdx.x; d < 512; d += 256) {
        int i2 = d >> 1;
        float denom = powf(10000.0f, (float)(2 * i2) / 512.0f);
        float ang = (float)pos / denom;
        double a = (double)ang;
        g_R[(size_t)i * 512 + d] = (d & 1) ? (float)cos(a) : (float)sin(a);
    }
}

// pk[e][j] = R @ Wr_j  -> kbuf[e][j][:, 512:1024]
__global__ void __launch_bounds__(256) k_gemm_pk(const float* Wa, const float* Wb) {
    int z = blockIdx.z;
    int e = z / NLAY, layer = z % NLAY;
    GEMM_DECL
    const float* A = g_R + (size_t)row0 * 512;
    const float* B = (e ? Wb : Wa) + ((size_t)layer * 4 + 3) * 512 * 512 + col0;
    GEMM_NN(A, 512, B, 512, 512)
    GEMM_EPI
    float* C = g_kbuf[e][layer];
#pragma unroll
    for (int i = 0; i < 4; ++i) {
        float4 o = make_float4(rowv[i][0], rowv[i][1], rowv[i][2], rowv[i][3]);
        *(float4*)&C[(size_t)(row0 + (ty << 2) + i) * 1024 + 512 + col0 + (tx << 2)] = o;
    }
}

// state = emb[token]
__global__ void k_embed(const int* src, const float* emb, int s) {
    int e = blockIdx.y, m = blockIdx.x;
    int gpos = s * SEGN + m;
    int tok = e ? src[4095 - gpos] : src[gpos];
    const float4* sr = (const float4*)(emb + (size_t)tok * 512);
    float4* dst = (float4*)(g_state[e] + (size_t)m * 512);
    dst[threadIdx.x] = sr[threadIdx.x];
}

// Ap = [state@Wq + u | state@Wq + v]
__global__ void __launch_bounds__(256) k_gemm_q(const float* Wa, const float* Wb,
                                                const float* uva, const float* uvb, int layer) {
    int e = blockIdx.z;
    GEMM_DECL
    const float* A = g_state[e] + (size_t)row0 * 512;
    const float* B = (e ? Wb : Wa) + ((size_t)layer * 4 + 0) * 512 * 512 + col0;
    const float* uv = e ? uvb : uva;
    GEMM_NN(A, 512, B, 512, 512)
    GEMM_EPI
    float* Ap = g_Ap[e];
#pragma unroll
    for (int i = 0; i < 4; ++i) {
        int m = row0 + (ty << 2) + i;
        int n = col0 + (tx << 2);
        float4 o1 = make_float4(rowv[i][0] + uv[n],     rowv[i][1] + uv[n + 1],
                                rowv[i][2] + uv[n + 2], rowv[i][3] + uv[n + 3]);
        float4 o2 = make_float4(rowv[i][0] + uv[512 + n],     rowv[i][1] + uv[512 + n + 1],
                                rowv[i][2] + uv[512 + n + 2], rowv[i][3] + uv[512 + n + 3]);
        *(float4*)&Ap[(size_t)m * 1024 + n] = o1;
        *(float4*)&Ap[(size_t)m * 1024 + 512 + n] = o2;
    }
}

// k = full@Wk -> kbuf[:, :512];  v = full@Wv -> vbuf   (full = [hist_old; hist_new; state])
__global__ void __launch_bounds__(256) k_gemm_kv(const float* Wa, const float* Wb,
                                                 int layer, int slot_old, int slot_new) {
    int e = blockIdx.z;
    GEMM_DECL
    const float* A;
    if (row0 < 512)       A = g_hist[e][layer][slot_old] + (size_t)row0 * 512;
    else if (row0 < 1024) A = g_hist[e][layer][slot_new] + (size_t)(row0 - 512) * 512;
    else                  A = g_state[e] + (size_t)(row0 - 1024) * 512;
    const float* Wbase = (e ? Wb : Wa) + (size_t)layer * 4 * 512 * 512;
    const float* B; float* C; int ldc, ccol;
    if (col0 < 512) { B = Wbase + (size_t)1 * 512 * 512 + col0;        C = g_kbuf[e][layer]; ldc = 1024; ccol = col0; }
    else            { B = Wbase + (size_t)2 * 512 * 512 + (col0 - 512); C = g_vbuf[e];       ldc = 512;  ccol = col0 - 512; }
    GEMM_NN(A, 512, B, 512, 512)
    GEMM_EPI
#pragma unroll
    for (int i = 0; i < 4; ++i) {
        float4 o = make_float4(rowv[i][0], rowv[i][1], rowv[i][2], rowv[i][3]);
        *(float4*)&C[(size_t)(row0 + (ty << 2) + i) * ldc + ccol + (tx << 2)] = o;
    }
}

// record layer-input state into history slot (after kv consumed the old slot)
__global__ void k_copy_rec(int layer, int slot) {
    int e = blockIdx.y, m = blockIdx.x;
    const float4* s4 = (const float4*)(g_state[e] + (size_t)m * 512);
    float4* d4 = (float4*)(g_hist[e][layer][slot] + (size_t)m * 512);
    d4[threadIdx.x] = s4[threadIdx.x];
}

// scores = Ap @ kbuf^T * scale
__global__ void __launch_bounds__(256) k_gemm_scores(int layer) {
    int e = blockIdx.z;
    GEMM_DECL
    const float* A = g_Ap[e] + (size_t)row0 * 1024;
    const float* B = g_kbuf[e][layer] + (size_t)col0 * 1024;
    GEMM_NT(A, 1024, B, 1024, 1024)
    GEMM_EPI
    const float scale = 0.04419417382415922f;   // 1/sqrt(512)
    float* C = g_scores[e];
#pragma unroll
    for (int i = 0; i < 4; ++i) {
        float4 o = make_float4(rowv[i][0] * scale, rowv[i][1] * scale,
                               rowv[i][2] * scale, rowv[i][3] * scale);
        *(float4*)&C[(size_t)(row0 + (ty << 2) + i) * FULLN + col0 + (tx << 2)] = o;
    }
}

// row softmax over [vstart, 1536); zeros below vstart (== -1e9 bias)
__global__ void k_softmax(int vstart) {
    int e = blockIdx.y, tid = threadIdx.x;
    float* s = g_scores[e] + (size_t)blockIdx.x * FULLN;
    __shared__ float red[256];
    float mx = -3.0e38f;
    for (int c = vstart + tid; c < FULLN; c += 256) mx = fmaxf(mx, s[c]);
    red[tid] = mx; __syncthreads();
    for (int o = 128; o; o >>= 1) { if (tid < o) red[tid] = fmaxf(red[tid], red[tid + o]); __syncthreads(); }
    mx = red[0]; __syncthreads();
    float sum = 0.f;
    for (int c = vstart + tid; c < FULLN; c += 256) { float v = expf(s[c] - mx); s[c] = v; sum += v; }
    red[tid] = sum; __syncthreads();
    for (int o = 128; o; o >>= 1) { if (tid < o) red[tid] += red[tid + o]; __syncthreads(); }
    float inv = 1.f / red[0];
    for (int c = tid; c < vstart; c += 256) s[c] = 0.f;
    for (int c = vstart + tid; c < FULLN; c += 256) s[c] *= inv;
}

// av = attn @ v
__global__ void __launch_bounds__(256) k_gemm_av() {
    int e = blockIdx.z;
    GEMM_DECL
    const float* A = g_scores[e] + (size_t)row0 * FULLN;
    const float* B = g_vbuf[e] + col0;
    GEMM_NN(A, FULLN, B, 512, FULLN)
    GEMM_EPI
#pragma unroll
    for (int i = 0; i < 4; ++i) {
        float4 o = make_float4(rowv[i][0], rowv[i][1], rowv[i][2], rowv[i][3]);
        *(float4*)&g_av[e][(size_t)(row0 + (ty << 2) + i) * 512 + col0 + (tx << 2)] = o;
    }
}

// t = state + av @ Wo
__global__ void __launch_bounds__(256) k_gemm_wo(const float* Wa, const float* Wb, int layer) {
    int e = blockIdx.z;
    GEMM_DECL
    const float* A = g_av[e] + (size_t)row0 * 512;
    const float* B = (e ? Wb : Wa) + (size_t)layer * 512 * 512 + col0;
    GEMM_NN(A, 512, B, 512, 512)
    GEMM_EPI
#pragma unroll
    for (int i = 0; i < 4; ++i) {
        int m = row0 + (ty << 2) + i, n = col0 + (tx << 2);
        float4 st = *(const float4*)&g_state[e][(size_t)m * 512 + n];
        float4 o = make_float4(rowv[i][0] + st.x, rowv[i][1] + st.y,
                               rowv[i][2] + st.z, rowv[i][3] + st.w);
        *(float4*)&g_t[e][(size_t)m * 512 + n] = o;
    }
}

// mid = relu(h @ W1)
__global__ void __launch_bounds__(256) k_gemm_w1(const float* Wa, const float* Wb, int layer) {
    int e = blockIdx.z;
    GEMM_DECL
    const float* A = g_h[e] + (size_t)row0 * 512;
    const float* B = (e ? Wb : Wa) + (size_t)layer * 512 * FFD + col0;
    GEMM_NN(A, 512, B, FFD, 512)
    GEMM_EPI
#pragma unroll
    for (int i = 0; i < 4; ++i) {
        float4 o = make_float4(fmaxf(rowv[i][0], 0.f), fmaxf(rowv[i][1], 0.f),
                               fmaxf(rowv[i][2], 0.f), fmaxf(rowv[i][3], 0.f));
        *(float4*)&g_mid[e][(size_t)(row0 + (ty << 2) + i) * FFD + col0 + (tx << 2)] = o;
    }
}

// t2 = h + mid @ W2
__global__ void __launch_bounds__(256) k_gemm_w2(const float* Wa, const float* Wb, int layer) {
    int e = blockIdx.z;
    GEMM_DECL
    const float* A = g_mid[e] + (size_t)row0 * FFD;
    const float* B = (e ? Wb : Wa) + (size_t)layer * FFD * 512 + col0;
    GEMM_NN(A, FFD, B, 512, FFD)
    GEMM_EPI
#pragma unroll
    for (int i = 0; i < 4; ++i) {
        int m = row0 + (ty << 2) + i, n = col0 + (tx << 2);
        float4 hh = *(const float4*)&g_h[e][(size_t)m * 512 + n];
        float4 o = make_float4(rowv[i][0] + hh.x, rowv[i][1] + hh.y,
                               rowv[i][2] + hh.z, rowv[i][3] + hh.w);
        *(float4*)&g_t2[e][(size_t)m * 512 + n] = o;
    }
}

// layernorm. mode 0: g_t -> g_h (ln rows 0,1). mode 1: g_t2 -> g_state (ln rows 2,3).
__global__ void k_ln(const float* lnA, const float* lnB, int layer, int which, int mode) {
    int e = blockIdx.y, row = blockIdx.x, tid = threadIdx.x;
    const float* in = (mode ? g_t2[e] : g_t[e]) + (size_t)row * 512;
    float* out = (mode ? g_state[e] : g_h[e]) + (size_t)row * 512;
    const float* ln = (e ? lnB : lnA) + ((size_t)layer * 4 + 2 * which) * 512;
    __shared__ float red[256];
    float x0 = in[tid], x1 = in[tid + 256];
    red[tid] = x0 + x1; __syncthreads();
    for (int o = 128; o; o >>= 1) { if (tid < o) red[tid] += red[tid + o]; __syncthreads(); }
    float mu = red[0] * (1.f / 512.f); __syncthreads();
    float d0 = x0 - mu, d1 = x1 - mu;
    red[tid] = d0 * d0 + d1 * d1; __syncthreads();
    for (int o = 128; o; o >>= 1) { if (tid < o) red[tid] += red[tid + o]; __syncthreads(); }
    float r = rsqrtf(red[0] * (1.f / 512.f) + 1e-5f);
    out[tid]       = d0 * r * ln[tid]       + ln[512 + tid];
    out[tid + 256] = d1 * r * ln[tid + 256] + ln[512 + tid + 256];
}

// last-layer LN2 writes directly to output with fwd/rev mapping
__global__ void k_ln_final(const float* lnA, const float* lnB, int layer, int s, float* out) {
    int e = blockIdx.y, row = blockIdx.x, tid = threadIdx.x;
    const float* in = g_t2[e] + (size_t)row * 512;
    const float* ln = (e ? lnB : lnA) + ((size_t)layer * 4 + 2) * 512;
    __shared__ float red[256];
    float x0 = in[tid], x1 = in[tid + 256];
    red[tid] = x0 + x1; __syncthreads();
    for (int o = 128; o; o >>= 1) { if (tid < o) red[tid] += red[tid + o]; __syncthreads(); }
    float mu = red[0] * (1.f / 512.f); __syncthreads();
    float d0 = x0 - mu, d1 = x1 - mu;
    red[tid] = d0 * d0 + d1 * d1; __syncthreads();
    for (int o = 128; o; o >>= 1) { if (tid < o) red[tid] += red[tid + o]; __syncthreads(); }
    float r = rsqrtf(red[0] * (1.f / 512.f) + 1e-5f);
    int g = s * SEGN + row;
    float* dst = e ? (out + (size_t)(4095 - g) * 1024 + 512) : (out + (size_t)g * 1024);
    dst[tid]       = d0 * r * ln[tid]       + ln[512 + tid];
    dst[tid + 256] = d1 * r * ln[tid + 256] + ln[512 + tid + 256];
}

// ---------------- host orchestration (graph-capturable: launches only) ----------------
extern "C" void kernel_launch(void* const* d_in, const int* in_sizes, int n_in,
                              void* d_out, int out_size) {
    const int*   src  = (const int*)d_in[0];
    const float* emb  = (const float*)d_in[2];
    const float* Wq_a = (const float*)d_in[3];
    const float* Wo_a = (const float*)d_in[4];
    const float* W1_a = (const float*)d_in[5];
    const float* W2_a = (const float*)d_in[6];
    const float* ln_a = (const float*)d_in[7];
    const float* uv_a = (const float*)d_in[8];
    const float* Wq_b = (const float*)d_in[9];
    const float* Wo_b = (const float*)d_in[10];
    const float* W1_b = (const float*)d_in[11];
    const float* W2_b = (const float*)d_in[12];
    const float* ln_b = (const float*)d_in[13];
    const float* uv_b = (const float*)d_in[14];
    float* out = (float*)d_out;

    k_R<<<FULLN, 256>>>();
    k_gemm_pk<<<dim3(8, 24, 12), 256>>>(Wq_a, Wq_b);   // segment-invariant pk, hoisted

    for (int s = 0; s < NSEGS; ++s) {
        k_embed<<<dim3(512, 2), 128>>>(src, emb, s);
        int vstart = 1024 - (s < 2 ? s : 2) * 512;
        int slot_old = s & 1, slot_new = (s & 1) ^ 1;
        for (int j = 0; j < NLAY; ++j) {
            k_gemm_q     <<<dim3(8, 8, 2),   256>>>(Wq_a, Wq_b, uv_a, uv_b, j);
            k_gemm_kv    <<<dim3(16, 24, 2), 256>>>(Wq_a, Wq_b, j, slot_old, slot_new);
            k_copy_rec   <<<dim3(512, 2),    128>>>(j, slot_old);
            k_gemm_scores<<<dim3(24, 8, 2),  256>>>(j);
            k_softmax    <<<dim3(512, 2),    256>>>(vstart);
            k_gemm_av    <<<dim3(8, 8, 2),   256>>>();
            k_gemm_wo    <<<dim3(8, 8, 2),   256>>>(Wo_a, Wo_b, j);
            k_ln         <<<dim3(512, 2),    256>>>(ln_a, ln_b, j, 0, 0);
            k_gemm_w1    <<<dim3(32, 8, 2),  256>>>(W1_a, W1_b, j);
            k_gemm_w2    <<<dim3(8, 8, 2),   256>>>(W2_a, W2_b, j);
            if (j < NLAY - 1) k_ln<<<dim3(512, 2), 256>>>(ln_a, ln_b, j, 1, 1);
            else              k_ln_final<<<dim3(512, 2), 256>>>(ln_a, ln_b, j, s, out);
        }
    }
}

// round 4
// speedup vs baseline: 1.4403x; 1.1482x over previous
#include <cuda_runtime.h>
#include <math.h>

#define SEGN 512
#define DDIM 512
#define NLAY 6
#define NSEGS 8
#define FFD 2048
#define FULLN 1536

typedef unsigned long long u64;

// ---------------- packed fp32 math (Blackwell FFMA2, PTX-only) ----------------
__device__ __forceinline__ u64 ffma2(u64 a, u64 b, u64 c) {
    u64 d;
    asm("fma.rn.f32x2 %0, %1, %2, %3;" : "=l"(d) : "l"(a), "l"(b), "l"(c));
    return d;
}
__device__ __forceinline__ u64 pack2(float x, float y) {
    u64 d;
    asm("mov.b64 %0, {%1, %2};" : "=l"(d)
        : "r"(__float_as_uint(x)), "r"(__float_as_uint(y)));
    return d;
}
__device__ __forceinline__ float2 unpk(u64 a) {
    unsigned lo, hi;
    asm("mov.b64 {%0, %1}, %2;" : "=r"(lo), "=r"(hi) : "l"(a));
    return make_float2(__uint_as_float(lo), __uint_as_float(hi));
}

// ---------------- scratch (device globals; no allocations allowed) ----------------
__device__ float g_R[FULLN * 512];                    // flipped sinusoid table
__device__ float g_state[2][SEGN * DDIM];             // current segment state per encoder
__device__ float g_Ap[2][SEGN * 1024];                // [q+u | q+v]
__device__ float g_kbuf[2][NLAY][2][FULLN * 1024];    // ping-pong [k | pk] per layer
__device__ float g_vbuf[2][NLAY][2][FULLN * DDIM];    // ping-pong v per layer
__device__ float g_scores[2][SEGN * FULLN];           // scores / attn (in place)
__device__ float g_av[2][SEGN * DDIM];                // attn @ v
__device__ float g_t[2][SEGN * DDIM];                 // pre-LN1
__device__ float g_h[2][SEGN * DDIM];                 // post-LN1
__device__ float g_mid[2][SEGN * FFD];                // relu(h@W1)
__device__ float g_t2[2][SEGN * DDIM];                // pre-LN2

// ---------------- GEMM core: 64x64 tile, BK=16, f32x2 4x4 microtile, 256 thr ----------------
#define GEMM_DECL                                                              \
    __shared__ float As[16][68];                                               \
    __shared__ float Bs[16][68];                                               \
    u64 acc[2][4] = {{0ull,0ull,0ull,0ull},{0ull,0ull,0ull,0ull}};             \
    const int t  = threadIdx.x;                                                \
    const int tx = t & 15, ty = t >> 4;                                        \
    const int ar = t >> 2, ac = (t & 3) << 2;                                  \
    const int br = t >> 4, bc = (t & 15) << 2;                                 \
    const int row0 = blockIdx.y << 6, col0 = blockIdx.x << 6;                  \
    (void)br; (void)bc; (void)row0; (void)col0;

#define INNER16                                                                \
    _Pragma("unroll")                                                          \
    for (int kk = 0; kk < 16; ++kk) {                                          \
        float4 a4 = *(const float4*)&As[kk][ty << 2];                          \
        float4 b4 = *(const float4*)&Bs[kk][tx << 2];                          \
        u64 a01 = pack2(a4.x, a4.y);                                           \
        u64 a23 = pack2(a4.z, a4.w);                                           \
        u64 bb;                                                                \
        bb = pack2(b4.x, b4.x);                                                \
        acc[0][0] = ffma2(a01, bb, acc[0][0]);                                 \
        acc[1][0] = ffma2(a23, bb, acc[1][0]);                                 \
        bb = pack2(b4.y, b4.y);                                                \
        acc[0][1] = ffma2(a01, bb, acc[0][1]);                                 \
        acc[1][1] = ffma2(a23, bb, acc[1][1]);                                 \
        bb = pack2(b4.z, b4.z);                                                \
        acc[0][2] = ffma2(a01, bb, acc[0][2]);                                 \
        acc[1][2] = ffma2(a23, bb, acc[1][2]);                                 \
        bb = pack2(b4.w, b4.w);                                                \
        acc[0][3] = ffma2(a01, bb, acc[0][3]);                                 \
        acc[1][3] = ffma2(a23, bb, acc[1][3]);                                 \
    }

// A row-major [M,Ktot] (pre-offset to row0), B row-major [Ktot,N] (pre-offset to col0)
#define GEMM_NN(Aptr, lda, Bptr, ldb, Ktot) {                                  \
    float4 pa = *(const float4*)((Aptr) + (size_t)ar * (lda) + ac);            \
    float4 pb = *(const float4*)((Bptr) + (size_t)br * (ldb) + bc);            \
    for (int kt = 0; kt < (Ktot); kt += 16) {                                  \
        As[ac+0][ar] = pa.x; As[ac+1][ar] = pa.y;                              \
        As[ac+2][ar] = pa.z; As[ac+3][ar] = pa.w;                              \
        *(float4*)&Bs[br][bc] = pb;                                            \
        __syncthreads();                                                       \
        if (kt + 16 < (Ktot)) {                                                \
            pa = *(const float4*)((Aptr) + (size_t)ar * (lda) + kt + 16 + ac); \
            pb = *(const float4*)((Bptr) + (size_t)(kt + 16 + br) * (ldb) + bc); \
        }                                                                      \
        INNER16                                                                \
        __syncthreads();                                                       \
    } }

// A row-major [M,Ktot] (pre-offset to row0), B row-major [N,Ktot] (pre-offset to col0 rows)
#define GEMM_NT(Aptr, lda, Bptr, ldb, Ktot) {                                  \
    float4 pa = *(const float4*)((Aptr) + (size_t)ar * (lda) + ac);            \
    float4 pb = *(const float4*)((Bptr) + (size_t)ar * (ldb) + ac);            \
    for (int kt = 0; kt < (Ktot); kt += 16) {                                  \
        As[ac+0][ar] = pa.x; As[ac+1][ar] = pa.y;                              \
        As[ac+2][ar] = pa.z; As[ac+3][ar] = pa.w;                              \
        Bs[ac+0][ar] = pb.x; Bs[ac+1][ar] = pb.y;                              \
        Bs[ac+2][ar] = pb.z; Bs[ac+3][ar] = pb.w;                              \
        __syncthreads();                                                       \
        if (kt + 16 < (Ktot)) {                                                \
            pa = *(const float4*)((Aptr) + (size_t)ar * (lda) + kt + 16 + ac); \
            pb = *(const float4*)((Bptr) + (size_t)ar * (ldb) + kt + 16 + ac); \
        }                                                                      \
        INNER16                                                                \
        __syncthreads();                                                       \
    } }

#define GEMM_EPI                                                               \
    float rowv[4][4];                                                          \
    _Pragma("unroll")                                                          \
    for (int c = 0; c < 4; ++c) {                                              \
        float2 v0 = unpk(acc[0][c]);                                           \
        float2 v1 = unpk(acc[1][c]);                                           \
        rowv[0][c] = v0.x; rowv[1][c] = v0.y;                                  \
        rowv[2][c] = v1.x; rowv[3][c] = v1.y;                                  \
    }

// ---------------- init: sinusoid table (flipped) ----------------
__global__ void k_R() {
    int i = blockIdx.x;              // output row (already flipped)
    int pos = FULLN - 1 - i;
    for (int d = threadIdx.x; d < 512; d += 256) {
        int i2 = d >> 1;
        float denom = powf(10000.0f, (float)(2 * i2) / 512.0f);
        float ang = (float)pos / denom;
        double a = (double)ang;
        g_R[(size_t)i * 512 + d] = (d & 1) ? (float)cos(a) : (float)sin(a);
    }
}

// pk[e][j] = R @ Wr_j  -> BOTH ping-pong kbuf buffers, cols 512..1024
__global__ void __launch_bounds__(256) k_gemm_pk(const float* Wa, const float* Wb) {
    int z = blockIdx.z;
    int e = z / NLAY, layer = z % NLAY;
    GEMM_DECL
    const float* A = g_R + (size_t)row0 * 512;
    const float* B = (e ? Wb : Wa) + ((size_t)layer * 4 + 3) * 262144 + col0;
    GEMM_NN(A, 512, B, 512, 512)
    GEMM_EPI
#pragma unroll
    for (int i = 0; i < 4; ++i) {
        float4 o = make_float4(rowv[i][0], rowv[i][1], rowv[i][2], rowv[i][3]);
        size_t off = (size_t)(row0 + (ty << 2) + i) * 1024 + 512 + col0 + (tx << 2);
        *(float4*)&g_kbuf[e][layer][0][off] = o;
        *(float4*)&g_kbuf[e][layer][1][off] = o;
    }
}

// state = emb[token]
__global__ void k_embed(const int* src, const float* emb, int s) {
    int e = blockIdx.y, m = blockIdx.x;
    int gpos = s * SEGN + m;
    int tok = e ? src[4095 - gpos] : src[gpos];
    const float4* sr = (const float4*)(emb + (size_t)tok * 512);
    float4* dst = (float4*)(g_state[e] + (size_t)m * 512);
    dst[threadIdx.x] = sr[threadIdx.x];
}

// shift cached k/v: buf[prev] rows 512..1536 -> buf[cur] rows 0..1024 (k half + v)
__global__ void k_shift(int prev, int cur) {
    int e = blockIdx.z;
    int l = blockIdx.y >> 1, w = blockIdx.y & 1;
    int i = blockIdx.x * 256 + threadIdx.x;     // float4 index in 1024x512 region
    int row = i >> 7;
    int c4 = (i & 127) << 2;
    if (w == 0) {
        float4 v = *(const float4*)&g_kbuf[e][l][prev][(size_t)(row + 512) * 1024 + c4];
        *(float4*)&g_kbuf[e][l][cur][(size_t)row * 1024 + c4] = v;
    } else {
        float4 v = *(const float4*)&g_vbuf[e][l][prev][(size_t)(row + 512) * 512 + c4];
        *(float4*)&g_vbuf[e][l][cur][(size_t)row * 512 + c4] = v;
    }
}

// merged q/k/v for CURRENT segment only:
// col block 0: q -> Ap (+u|+v); 1: k -> kbuf[buf] rows 1024.., cols 0..512;
// 2: v -> vbuf[buf] rows 1024..
__global__ void __launch_bounds__(256) k_gemm_qkv(const float* Wa, const float* Wb,
                                                  const float* uva, const float* uvb,
                                                  int j, int buf) {
    int e = blockIdx.z;
    GEMM_DECL
    const int mat = col0 >> 9, n0 = col0 & 511;
    const float* A = g_state[e] + (size_t)row0 * 512;
    const float* B = (e ? Wb : Wa) + ((size_t)j * 4 + mat) * 262144 + n0;
    GEMM_NN(A, 512, B, 512, 512)
    GEMM_EPI
    if (mat == 0) {
        const float* uv = e ? uvb : uva;
        float* Ap = g_Ap[e];
#pragma unroll
        for (int i = 0; i < 4; ++i) {
            int m = row0 + (ty << 2) + i;
            int n = n0 + (tx << 2);
            float4 o1 = make_float4(rowv[i][0] + uv[n],     rowv[i][1] + uv[n + 1],
                                    rowv[i][2] + uv[n + 2], rowv[i][3] + uv[n + 3]);
            float4 o2 = make_float4(rowv[i][0] + uv[512 + n],     rowv[i][1] + uv[512 + n + 1],
                                    rowv[i][2] + uv[512 + n + 2], rowv[i][3] + uv[512 + n + 3]);
            *(float4*)&Ap[(size_t)m * 1024 + n] = o1;
            *(float4*)&Ap[(size_t)m * 1024 + 512 + n] = o2;
        }
    } else if (mat == 1) {
        float* C = g_kbuf[e][j][buf];
#pragma unroll
        for (int i = 0; i < 4; ++i) {
            float4 o = make_float4(rowv[i][0], rowv[i][1], rowv[i][2], rowv[i][3]);
            *(float4*)&C[(size_t)(1024 + row0 + (ty << 2) + i) * 1024 + n0 + (tx << 2)] = o;
        }
    } else {
        float* C = g_vbuf[e][j][buf];
#pragma unroll
        for (int i = 0; i < 4; ++i) {
            float4 o = make_float4(rowv[i][0], rowv[i][1], rowv[i][2], rowv[i][3]);
            *(float4*)&C[(size_t)(1024 + row0 + (ty << 2) + i) * 512 + n0 + (tx << 2)] = o;
        }
    }
}

// scores = Ap @ kbuf[buf]^T * scale
__global__ void __launch_bounds__(256) k_gemm_scores(int layer, int buf) {
    int e = blockIdx.z;
    GEMM_DECL
    const float* A = g_Ap[e] + (size_t)row0 * 1024;
    const float* B = g_kbuf[e][layer][buf] + (size_t)col0 * 1024;
    GEMM_NT(A, 1024, B, 1024, 1024)
    GEMM_EPI
    const float scale = 0.04419417382415922f;   // 1/sqrt(512)
    float* C = g_scores[e];
#pragma unroll
    for (int i = 0; i < 4; ++i) {
        float4 o = make_float4(rowv[i][0] * scale, rowv[i][1] * scale,
                               rowv[i][2] * scale, rowv[i][3] * scale);
        *(float4*)&C[(size_t)(row0 + (ty << 2) + i) * FULLN + col0 + (tx << 2)] = o;
    }
}

// row softmax over [vstart, 1536); zeros below vstart (== -1e9 bias)
__global__ void k_softmax(int vstart) {
    int e = blockIdx.y, tid = threadIdx.x;
    float* s = g_scores[e] + (size_t)blockIdx.x * FULLN;
    __shared__ float red[256];
    float mx = -3.0e38f;
    for (int c = vstart + tid; c < FULLN; c += 256) mx = fmaxf(mx, s[c]);
    red[tid] = mx; __syncthreads();
    for (int o = 128; o; o >>= 1) { if (tid < o) red[tid] = fmaxf(red[tid], red[tid + o]); __syncthreads(); }
    mx = red[0]; __syncthreads();
    float sum = 0.f;
    for (int c = vstart + tid; c < FULLN; c += 256) { float v = expf(s[c] - mx); s[c] = v; sum += v; }
    red[tid] = sum; __syncthreads();
    for (int o = 128; o; o >>= 1) { if (tid < o) red[tid] += red[tid + o]; __syncthreads(); }
    float inv = 1.f / red[0];
    for (int c = tid; c < vstart; c += 256) s[c] = 0.f;
    for (int c = vstart + tid; c < FULLN; c += 256) s[c] *= inv;
}

// av = attn @ v
__global__ void __launch_bounds__(256) k_gemm_av(int layer, int buf) {
    int e = blockIdx.z;
    GEMM_DECL
    const float* A = g_scores[e] + (size_t)row0 * FULLN;
    const float* B = g_vbuf[e][layer][buf] + col0;
    GEMM_NN(A, FULLN, B, 512, FULLN)
    GEMM_EPI
#pragma unroll
    for (int i = 0; i < 4; ++i) {
        float4 o = make_float4(rowv[i][0], rowv[i][1], rowv[i][2], rowv[i][3]);
        *(float4*)&g_av[e][(size_t)(row0 + (ty << 2) + i) * 512 + col0 + (tx << 2)] = o;
    }
}

// t = state + av @ Wo
__global__ void __launch_bounds__(256) k_gemm_wo(const float* Wa, const float* Wb, int layer) {
    int e = blockIdx.z;
    GEMM_DECL
    const float* A = g_av[e] + (size_t)row0 * 512;
    const float* B = (e ? Wb : Wa) + (size_t)layer * 262144 + col0;
    GEMM_NN(A, 512, B, 512, 512)
    GEMM_EPI
#pragma unroll
    for (int i = 0; i < 4; ++i) {
        int m = row0 + (ty << 2) + i, n = col0 + (tx << 2);
        float4 st = *(const float4*)&g_state[e][(size_t)m * 512 + n];
        float4 o = make_float4(rowv[i][0] + st.x, rowv[i][1] + st.y,
                               rowv[i][2] + st.z, rowv[i][3] + st.w);
        *(float4*)&g_t[e][(size_t)m * 512 + n] = o;
    }
}

// mid = relu(h @ W1)
__global__ void __launch_bounds__(256) k_gemm_w1(const float* Wa, const float* Wb, int layer) {
    int e = blockIdx.z;
    GEMM_DECL
    const float* A = g_h[e] + (size_t)row0 * 512;
    const float* B = (e ? Wb : Wa) + (size_t)layer * 512 * FFD + col0;
    GEMM_NN(A, 512, B, FFD, 512)
    GEMM_EPI
#pragma unroll
    for (int i = 0; i < 4; ++i) {
        float4 o = make_float4(fmaxf(rowv[i][0], 0.f), fmaxf(rowv[i][1], 0.f),
                               fmaxf(rowv[i][2], 0.f), fmaxf(rowv[i][3], 0.f));
        *(float4*)&g_mid[e][(size_t)(row0 + (ty << 2) + i) * FFD + col0 + (tx << 2)] = o;
    }
}

// t2 = h + mid @ W2
__global__ void __launch_bounds__(256) k_gemm_w2(const float* Wa, const float* Wb, int layer) {
    int e = blockIdx.z;
    GEMM_DECL
    const float* A = g_mid[e] + (size_t)row0 * FFD;
    const float* B = (e ? Wb : Wa) + (size_t)layer * FFD * 512 + col0;
    GEMM_NN(A, FFD, B, 512, FFD)
    GEMM_EPI
#pragma unroll
    for (int i = 0; i < 4; ++i) {
        int m = row0 + (ty << 2) + i, n = col0 + (tx << 2);
        float4 hh = *(const float4*)&g_h[e][(size_t)m * 512 + n];
        float4 o = make_float4(rowv[i][0] + hh.x, rowv[i][1] + hh.y,
                               rowv[i][2] + hh.z, rowv[i][3] + hh.w);
        *(float4*)&g_t2[e][(size_t)m * 512 + n] = o;
    }
}

// layernorm. mode 0: g_t -> g_h (ln rows 0,1). mode 1: g_t2 -> g_state (ln rows 2,3).
__global__ void k_ln(const float* lnA, const float* lnB, int layer, int which, int mode) {
    int e = blockIdx.y, row = blockIdx.x, tid = threadIdx.x;
    const float* in = (mode ? g_t2[e] : g_t[e]) + (size_t)row * 512;
    float* out = (mode ? g_state[e] : g_h[e]) + (size_t)row * 512;
    const float* ln = (e ? lnB : lnA) + ((size_t)layer * 4 + 2 * which) * 512;
    __shared__ float red[256];
    float x0 = in[tid], x1 = in[tid + 256];
    red[tid] = x0 + x1; __syncthreads();
    for (int o = 128; o; o >>= 1) { if (tid < o) red[tid] += red[tid + o]; __syncthreads(); }
    float mu = red[0] * (1.f / 512.f); __syncthreads();
    float d0 = x0 - mu, d1 = x1 - mu;
    red[tid] = d0 * d0 + d1 * d1; __syncthreads();
    for (int o = 128; o; o >>= 1) { if (tid < o) red[tid] += red[tid + o]; __syncthreads(); }
    float r = rsqrtf(red[0] * (1.f / 512.f) + 1e-5f);
    out[tid]       = d0 * r * ln[tid]       + ln[512 + tid];
    out[tid + 256] = d1 * r * ln[tid + 256] + ln[512 + tid + 256];
}

// last-layer LN2 writes directly to output with fwd/rev mapping
__global__ void k_ln_final(const float* lnA, const float* lnB, int layer, int s, float* out) {
    int e = blockIdx.y, row = blockIdx.x, tid = threadIdx.x;
    const float* in = g_t2[e] + (size_t)row * 512;
    const float* ln = (e ? lnB : lnA) + ((size_t)layer * 4 + 2) * 512;
    __shared__ float red[256];
    float x0 = in[tid], x1 = in[tid + 256];
    red[tid] = x0 + x1; __syncthreads();
    for (int o = 128; o; o >>= 1) { if (tid < o) red[tid] += red[tid + o]; __syncthreads(); }
    float mu = red[0] * (1.f / 512.f); __syncthreads();
    float d0 = x0 - mu, d1 = x1 - mu;
    red[tid] = d0 * d0 + d1 * d1; __syncthreads();
    for (int o = 128; o; o >>= 1) { if (tid < o) red[tid] += red[tid + o]; __syncthreads(); }
    float r = rsqrtf(red[0] * (1.f / 512.f) + 1e-5f);
    int g = s * SEGN + row;
    float* dst = e ? (out + (size_t)(4095 - g) * 1024 + 512) : (out + (size_t)g * 1024);
    dst[tid]       = d0 * r * ln[tid]       + ln[512 + tid];
    dst[tid + 256] = d1 * r * ln[tid + 256] + ln[512 + tid + 256];
}

// ---------------- host orchestration (graph-capturable: launches only) ----------------
extern "C" void kernel_launch(void* const* d_in, const int* in_sizes, int n_in,
                              void* d_out, int out_size) {
    const int*   src  = (const int*)d_in[0];
    const float* emb  = (const float*)d_in[2];
    const float* Wq_a = (const float*)d_in[3];
    const float* Wo_a = (const float*)d_in[4];
    const float* W1_a = (const float*)d_in[5];
    const float* W2_a = (const float*)d_in[6];
    const float* ln_a = (const float*)d_in[7];
    const float* uv_a = (const float*)d_in[8];
    const float* Wq_b = (const float*)d_in[9];
    const float* Wo_b = (const float*)d_in[10];
    const float* W1_b = (const float*)d_in[11];
    const float* W2_b = (const float*)d_in[12];
    const float* ln_b = (const float*)d_in[13];
    const float* uv_b = (const float*)d_in[14];
    float* out = (float*)d_out;

    k_R<<<FULLN, 256>>>();
    k_gemm_pk<<<dim3(8, 24, 12), 256>>>(Wq_a, Wq_b);   // segment-invariant pk, both buffers

    for (int s = 0; s < NSEGS; ++s) {
        int buf = s & 1, prev = buf ^ 1;
        if (s > 0) k_shift<<<dim3(512, 12, 2), 256>>>(prev, buf);
        k_embed<<<dim3(512, 2), 128>>>(src, emb, s);
        int vstart = 1024 - (s < 2 ? s : 2) * 512;
        for (int j = 0; j < NLAY; ++j) {
            k_gemm_qkv   <<<dim3(24, 8, 2), 256>>>(Wq_a, Wq_b, uv_a, uv_b, j, buf);
            k_gemm_scores<<<dim3(24, 8, 2), 256>>>(j, buf);
            k_softmax    <<<dim3(512, 2),   256>>>(vstart);
            k_gemm_av    <<<dim3(8, 8, 2),  256>>>(j, buf);
            k_gemm_wo    <<<dim3(8, 8, 2),  256>>>(Wo_a, Wo_b, j);
            k_ln         <<<dim3(512, 2),   256>>>(ln_a, ln_b, j, 0, 0);
            k_gemm_w1    <<<dim3(32, 8, 2), 256>>>(W1_a, W1_b, j);
            k_gemm_w2    <<<dim3(8, 8, 2),  256>>>(W2_a, W2_b, j);
            if (j < NLAY - 1) k_ln<<<dim3(512, 2), 256>>>(ln_a, ln_b, j, 1, 1);
            else              k_ln_final<<<dim3(512, 2), 256>>>(ln_a, ln_b, j, s, out);
        }
    }
}